// round 10
// baseline (speedup 1.0000x reference)
#include <cuda_runtime.h>
#include <cuda_bf16.h>
#include <cstdint>

#define BB   8
#define LL   50
#define BL   400
#define MM   32
#define NHOP 2
#define DD   64
#define HH   2
#define HDD  32
#define RR   20
#define NBLK 2

// ---------------- scratch ----------------------------------------------------
__device__ float g_item [BL*DD];
__device__ float g_osum [BL*DD];
__device__ float g_V    [BL*RR*DD];
__device__ float g_Q    [BL*DD];
__device__ float g_q    [BL*DD];
__device__ float g_k    [BL*DD];
__device__ float g_v    [BL*DD];
__device__ float g_ctx  [BL*DD];

__device__ __forceinline__ float lrelu(float x) { return x > 0.f ? x : 0.01f * x; }

#define BARP() asm volatile("bar.sync 1, 128;" ::: "memory")

// ---------------- V[bl,r,j] = sum_i item[bl,i] * R_r[i,j] --------------------
__global__ __launch_bounds__(256) void kv_rip(
    const float* __restrict__ rel, const float* __restrict__ E,
    const int* __restrict__ seq, int hop)
{
    __shared__ __align__(16) float IT[25*DD];
    const int u = blockIdx.x;
    const int r = u >> 4, c = u & 15;
    const int t = threadIdx.x;
    const int j = t & 63, gg = t >> 6;

    float Rj[64];
    const float* Rr = rel + (long)r*4096 + j;
    #pragma unroll
    for (int i = 0; i < 64; i++) Rj[i] = Rr[i*64];

    const int base = c * 25;
    for (int idx = t; idx < 25*DD; idx += 256) {
        int bl = base + (idx >> 6), d = idx & 63;
        IT[idx] = hop ? g_item[bl*DD + d] : E[(long)seq[bl]*DD + d];
    }
    __syncthreads();

    for (int l = gg; l < 25; l += 4) {
        const float4* it4 = (const float4*)(IT + l*DD);
        float a0 = 0.f, a1 = 0.f, a2 = 0.f, a3 = 0.f;
        #pragma unroll
        for (int k2 = 0; k2 < 4; k2++) {
            float4 x0 = it4[k2], x1 = it4[k2+4], x2 = it4[k2+8], x3 = it4[k2+12];
            a0 += x0.x*Rj[4*k2   ] + x0.y*Rj[4*k2+1 ] + x0.z*Rj[4*k2+2 ] + x0.w*Rj[4*k2+3 ];
            a1 += x1.x*Rj[4*k2+16] + x1.y*Rj[4*k2+17] + x1.z*Rj[4*k2+18] + x1.w*Rj[4*k2+19];
            a2 += x2.x*Rj[4*k2+32] + x2.y*Rj[4*k2+33] + x2.z*Rj[4*k2+34] + x2.w*Rj[4*k2+35];
            a3 += x3.x*Rj[4*k2+48] + x3.y*Rj[4*k2+49] + x3.z*Rj[4*k2+50] + x3.w*Rj[4*k2+51];
        }
        g_V[((long)(base + l)*RR + r)*DD + j] = (a0 + a1) + (a2 + a3);
    }
}

// ---------------- per-(b,l) hop update (256 threads) -------------------------
__global__ __launch_bounds__(256) void kh_rip(
    const float* __restrict__ E, const float* __restrict__ Wt,
    const int* __restrict__ mh, const int* __restrict__ mr, const int* __restrict__ mt,
    const int* __restrict__ seq, int hop, int last)
{
    __shared__ float sc[MM], pr[MM], u[DD], part[256], item_s[DD];
    const int bl = blockIdx.x, t = threadIdx.x;
    const int d = t & 63, quarter = t >> 6;
    const int mbase = (bl*NHOP + hop) * MM;

    if (t < DD)
        item_s[t] = hop ? g_item[bl*DD + t] : E[(long)seq[bl]*DD + t];

    const int m = t >> 3, e8 = t & 7;
    const int hid = mh[mbase + m], rid = mr[mbase + m];
    const float4* Vv = (const float4*)(g_V + ((long)bl*RR + rid) * DD) + e8*2;
    const float4* Hh = (const float4*)(E + (long)hid * DD) + e8*2;
    float4 va0 = Vv[0], va1 = Vv[1], ha0 = Hh[0], ha1 = Hh[1];

    float treg[8];
    const int* mtb = mt + mbase + quarter*8;
    #pragma unroll
    for (int m2 = 0; m2 < 8; m2++)
        treg[m2] = E[(long)mtb[m2]*DD + d];

    float acc = va0.x*ha0.x + va0.y*ha0.y + va0.z*ha0.z + va0.w*ha0.w
              + va1.x*ha1.x + va1.y*ha1.y + va1.z*ha1.z + va1.w*ha1.w;
    acc += __shfl_down_sync(0xffffffffu, acc, 4, 8);
    acc += __shfl_down_sync(0xffffffffu, acc, 2, 8);
    acc += __shfl_down_sync(0xffffffffu, acc, 1, 8);
    if (e8 == 0) sc[m] = acc;
    __syncthreads();

    if (t < 32) {
        float v = sc[t];
        float mx = v;
        #pragma unroll
        for (int o = 16; o; o >>= 1) mx = fmaxf(mx, __shfl_xor_sync(0xffffffffu, mx, o));
        float e = __expf(v - mx);
        float s = e;
        #pragma unroll
        for (int o = 16; o; o >>= 1) s += __shfl_xor_sync(0xffffffffu, s, o);
        pr[t] = e / s;
    }
    __syncthreads();

    float od = 0.f;
    #pragma unroll
    for (int m2 = 0; m2 < 8; m2++)
        od += pr[quarter*8 + m2] * treg[m2];
    part[t] = od;
    __syncthreads();
    if (t < DD) {
        float o = part[t] + part[t + 64] + part[t + 128] + part[t + 192];
        if (hop == 0) g_osum[bl*DD + t] = o;
        else          g_osum[bl*DD + t] += o;
        u[t] = o + item_s[t];
    }
    __syncthreads();

    if (!last) {
        const float4* wr = (const float4*)(Wt + d*DD) + quarter*4;
        const float4* uu = (const float4*)u + quarter*4;
        float a = 0.f;
        #pragma unroll
        for (int kk = 0; kk < 4; kk++) {
            float4 w = wr[kk], x = uu[kk];
            a += w.x*x.x + w.y*x.y + w.z*x.z + w.w*x.w;
        }
        part[t] = a;
        __syncthreads();
        if (t < DD)
            g_item[bl*DD + t] = lrelu(part[t] + part[t+64] + part[t+128] + part[t+192]);
    }
}

// ---------------- scan + fused per-row LN/qkv (warp-specialized) -------------
// 256 threads: warps 0-3 = serial scan (named barrier), warps 4-7 = LN+qkv
// consumers for finished rows (progress counter handoff). bb = 0 fixed.
__global__ __launch_bounds__(256) void ks2_rip(
    const float* __restrict__ W1, const float* __restrict__ W2,
    const float* __restrict__ uemb, const int* __restrict__ user,
    const float* __restrict__ pemb, const float* __restrict__ E,
    const int* __restrict__ seq,
    const float* __restrict__ lns, const float* __restrict__ lnb,
    const float* __restrict__ ipw, const float* __restrict__ ipb)
{
    __shared__ float S[LL*DD];
    __shared__ float Xs[LL*DD];
    __shared__ float AB[128];
    __shared__ float T[128];
    __shared__ float Qrow[4*DD];
    __shared__ volatile int vprog;

    const int b = blockIdx.x, t = threadIdx.x;
    const int wid = t >> 5, lane = t & 31;

    if (t == 128) vprog = 0;

    if (wid < 4) {
        // ---------------- producer: sequential scan ----------------
        const int i = t & 63, path = t >> 6;
        const float* W = path ? W2 : W1;
        const float4* wr = (const float4*)(W + i*DD);
        float4 wv[16];
        #pragma unroll
        for (int kk = 0; kk < 16; kk++) wv[kk] = wr[kk];

        for (int idx = t; idx < LL*DD; idx += 128) {
            int l = idx >> 6, d = idx & 63;
            S[idx] = E[(long)seq[b*LL + l]*DD + d] + g_osum[b*LL*DD + idx];
        }
        float c = uemb[(long)user[b] * DD + i];
        __syncthreads();   // all 256: init visible, S ready

        for (int st = 0; st < LL; st++) {
            float sv = S[st*DD + i];
            AB[path*64 + i] = path ? (sv * c) : (sv + c);
            BARP();
            if (t == 0 && st) vprog = st;    // rows < st fully written
            const float4* in = (const float4*)(AB + path*64);
            float a0 = 0.f, a1 = 0.f, a2 = 0.f, a3 = 0.f;
            #pragma unroll
            for (int kk = 0; kk < 16; kk += 4) {
                float4 x0 = in[kk],   x1 = in[kk+1], x2 = in[kk+2], x3 = in[kk+3];
                a0 += wv[kk  ].x*x0.x + wv[kk  ].y*x0.y + wv[kk  ].z*x0.z + wv[kk  ].w*x0.w;
                a1 += wv[kk+1].x*x1.x + wv[kk+1].y*x1.y + wv[kk+1].z*x1.z + wv[kk+1].w*x1.w;
                a2 += wv[kk+2].x*x2.x + wv[kk+2].y*x2.y + wv[kk+2].z*x2.z + wv[kk+2].w*x2.w;
                a3 += wv[kk+3].x*x3.x + wv[kk+3].y*x3.y + wv[kk+3].z*x3.z + wv[kk+3].w*x3.w;
            }
            float r = lrelu((a0 + a1) + (a2 + a3));
            T[path*64 + i] = r;
            BARP();
            float out = T[i] + T[64 + i];
            c = out;
            if (path == 0)
                Xs[st*DD + i] = out * 8.0f + pemb[st*DD + i];
        }
        BARP();
        if (t == 0) vprog = LL;
    } else {
        // ---------------- consumer: LN + qkv per finished row ----------------
        __syncthreads();   // matches producer's one full-block barrier
        const int cw = wid - 4;            // 0..3
        float* Qr = Qrow + cw*DD;
        for (int l = cw; l < LL; l += 4) {
            while (vprog < l + 1) __nanosleep(32);
            float x0 = Xs[l*DD + lane], x1 = Xs[l*DD + lane + 32];
            float s = x0 + x1;
            #pragma unroll
            for (int o = 16; o; o >>= 1) s += __shfl_xor_sync(0xffffffffu, s, o);
            float mean = s * (1.f/64.f);
            float e0 = x0 - mean, e1 = x1 - mean;
            float vs = e0*e0 + e1*e1;
            #pragma unroll
            for (int o = 16; o; o >>= 1) vs += __shfl_xor_sync(0xffffffffu, vs, o);
            float inv = rsqrtf(vs * (1.f/64.f) + 1e-8f);
            float q0 = e0 * inv * lns[lane]      + lnb[lane];
            float q1 = e1 * inv * lns[lane + 32] + lnb[lane + 32];
            const int row = b*LL + l;
            g_Q[row*DD + lane]      = q0;
            g_Q[row*DD + lane + 32] = q1;
            Qr[lane] = q0;
            Qr[lane + 32] = q1;
            __syncwarp();

            // 6 outputs per lane: o = k*32 + lane, k = 0..5 (q:0-1, k:2-3, v:4-5)
            float acc[6] = {0.f,0.f,0.f,0.f,0.f,0.f};
            const float4* qr4 = (const float4*)Qr;
            const float4* xr4 = (const float4*)(Xs + l*DD);
            #pragma unroll
            for (int kk = 0; kk < 16; kk++) {
                float4 qx = qr4[kk];
                float4 xx = xr4[kk];
                #pragma unroll
                for (int k = 0; k < 6; k++) {
                    int o = k*32 + lane;
                    const float4* w4 = (const float4*)(ipw + (long)o * DD);
                    float4 w = w4[kk];
                    float4 src = (k < 2) ? qx : xx;
                    acc[k] += w.x*src.x + w.y*src.y + w.z*src.z + w.w*src.w;
                }
            }
            #pragma unroll
            for (int k = 0; k < 6; k++) {
                int o = k*32 + lane;
                float r = acc[k] + ipb[o];
                if      (o < DD)   g_q[row*DD + o      ] = r;
                else if (o < 2*DD) g_k[row*DD + o - 64 ] = r;
                else               g_v[row*DD + o - 128] = r;
            }
        }
    }
}

// ---------------- causal attention, block = (b,h,qparity) --------------------
__global__ __launch_bounds__(256) void ka_rip()
{
    __shared__ float qh[LL*36], kh[LL*36], vh[LL*36];
    __shared__ float ps[8][52];
    const int blk = blockIdx.x;
    const int qs = blk & 1, h = (blk >> 1) & 1, b = blk >> 2;
    const int t = threadIdx.x;

    for (int idx = t; idx < LL*HDD; idx += 256) {
        int l = idx >> 5, d = idx & 31;
        int src = (b*LL + l)*DD + h*HDD + d;
        qh[l*36 + d] = g_q[src];
        kh[l*36 + d] = g_k[src];
        vh[l*36 + d] = g_v[src];
    }
    __syncthreads();

    const int w = t >> 5, lane = t & 31;
    const float scl = 0.17677669529663687f;
    for (int qi = 2*w + qs; qi < LL; qi += 16) {
        float4 qreg[8];
        const float4* qa = (const float4*)(qh + qi*36);
        #pragma unroll
        for (int kk = 0; kk < 8; kk++) qreg[kk] = qa[kk];

        int k0 = lane, k1 = lane + 32;
        float s0 = -3.0e38f, s1 = -3.0e38f;
        if (k0 <= qi) {
            const float4* ka = (const float4*)(kh + k0*36);
            float a = 0.f;
            #pragma unroll
            for (int kk = 0; kk < 8; kk++) {
                float4 kv = ka[kk];
                a += qreg[kk].x*kv.x + qreg[kk].y*kv.y + qreg[kk].z*kv.z + qreg[kk].w*kv.w;
            }
            s0 = a * scl;
        }
        if (k1 <= qi) {
            const float4* ka = (const float4*)(kh + k1*36);
            float a = 0.f;
            #pragma unroll
            for (int kk = 0; kk < 8; kk++) {
                float4 kv = ka[kk];
                a += qreg[kk].x*kv.x + qreg[kk].y*kv.y + qreg[kk].z*kv.z + qreg[kk].w*kv.w;
            }
            s1 = a * scl;
        }
        float mx = fmaxf(s0, s1);
        #pragma unroll
        for (int o = 16; o; o >>= 1) mx = fmaxf(mx, __shfl_xor_sync(0xffffffffu, mx, o));
        float e0 = (k0 <= qi) ? __expf(s0 - mx) : 0.f;
        float e1 = (k1 <= qi) ? __expf(s1 - mx) : 0.f;
        float sm = e0 + e1;
        #pragma unroll
        for (int o = 16; o; o >>= 1) sm += __shfl_xor_sync(0xffffffffu, sm, o);
        float inv = 1.f / sm;
        ps[w][k0] = e0 * inv;
        if (k1 < LL) ps[w][k1] = e1 * inv;
        __syncwarp();
        float acc = 0.f;
        for (int kj = 0; kj <= qi; kj++)
            acc += ps[w][kj] * vh[kj*36 + lane];
        g_ctx[(b*LL + qi)*DD + h*HDD + lane] = acc;
        __syncwarp();
    }
}

// ---------------- out-proj + residual + LN + FFN, then NEXT-block qkv or logits
__global__ __launch_bounds__(128) void km_rip(
    const float* __restrict__ opw, const float* __restrict__ opb,
    const float* __restrict__ fs,  const float* __restrict__ fb,
    const float* __restrict__ c1w, const float* __restrict__ c1b,
    const float* __restrict__ c2w, const float* __restrict__ c2b, int bb,
    int last, const float* __restrict__ E,
    const float* __restrict__ lls, const float* __restrict__ llb,
    const int* __restrict__ pos, const int* __restrict__ neg,
    float* __restrict__ out,
    const float* __restrict__ lns, const float* __restrict__ lnb,
    const float* __restrict__ ipw, const float* __restrict__ ipb)
{
    __shared__ float cs[DD], xr[DD], x2[DD], hdn[DD], part[128], Qs[DD];
    __shared__ float mv[2];
    const int bl = blockIdx.x, t = threadIdx.x;
    const int i = t & 63, half = t >> 6;
    if (t < DD) cs[t] = g_ctx[bl*DD + t];
    __syncthreads();

    {
        const float4* wr = (const float4*)(opw + ((long)bb*DD + i)*DD) + half*8;
        const float4* uu = (const float4*)cs + half*8;
        float a = 0.f;
        #pragma unroll
        for (int kk = 0; kk < 8; kk++) {
            float4 w = wr[kk], x = uu[kk];
            a += w.x*x.x + w.y*x.y + w.z*x.z + w.w*x.w;
        }
        part[t] = a;
    }
    __syncthreads();
    if (t < DD)
        xr[t] = part[t] + part[t+64] + opb[bb*DD + t] + g_Q[bl*DD + t];
    __syncthreads();

    if (t < 32) {
        float s = xr[t] + xr[t+32];
        #pragma unroll
        for (int o = 16; o; o >>= 1) s += __shfl_xor_sync(0xffffffffu, s, o);
        float mean = s * (1.f/64.f);
        float d0 = xr[t]-mean, d1 = xr[t+32]-mean;
        float vs = d0*d0 + d1*d1;
        #pragma unroll
        for (int o = 16; o; o >>= 1) vs += __shfl_xor_sync(0xffffffffu, vs, o);
        if (t == 0) { mv[0] = mean; mv[1] = rsqrtf(vs*(1.f/64.f) + 1e-8f); }
    }
    __syncthreads();
    if (t < DD)
        x2[t] = (xr[t] - mv[0]) * mv[1] * fs[bb*DD + t] + fb[bb*DD + t];
    __syncthreads();

    {
        const float4* wr = (const float4*)(c1w + ((long)bb*DD + i)*DD) + half*8;
        const float4* uu = (const float4*)x2 + half*8;
        float a = 0.f;
        #pragma unroll
        for (int kk = 0; kk < 8; kk++) {
            float4 w = wr[kk], x = uu[kk];
            a += w.x*x.x + w.y*x.y + w.z*x.z + w.w*x.w;
        }
        part[t] = a;
    }
    __syncthreads();
    if (t < DD) {
        float v = part[t] + part[t+64] + c1b[bb*DD + t];
        hdn[t] = v > 0.f ? v : 0.f;
    }
    __syncthreads();

    {
        const float4* wr = (const float4*)(c2w + ((long)bb*DD + i)*DD) + half*8;
        const float4* uu = (const float4*)hdn + half*8;
        float a = 0.f;
        #pragma unroll
        for (int kk = 0; kk < 8; kk++) {
            float4 w = wr[kk], x = uu[kk];
            a += w.x*x.x + w.y*x.y + w.z*x.z + w.w*x.w;
        }
        part[t] = a;
    }
    __syncthreads();
    if (t < DD)
        xr[t] = x2[t] + part[t] + part[t+64] + c2b[bb*DD + t];
    __syncthreads();

    if (t < 32) {
        float s = xr[t] + xr[t+32];
        #pragma unroll
        for (int o = 16; o; o >>= 1) s += __shfl_xor_sync(0xffffffffu, s, o);
        float mean = s * (1.f/64.f);
        float d0 = xr[t]-mean, d1 = xr[t+32]-mean;
        float vs = d0*d0 + d1*d1;
        #pragma unroll
        for (int o = 16; o; o >>= 1) vs += __shfl_xor_sync(0xffffffffu, vs, o);
        if (t == 0) { mv[0] = mean; mv[1] = rsqrtf(vs*(1.f/64.f) + 1e-8f); }
    }
    __syncthreads();

    if (!last) {
        const int b1 = bb + 1;
        if (t < DD) {
            float q = (xr[t] - mv[0]) * mv[1] * lns[b1*DD + t] + lnb[b1*DD + t];
            Qs[t] = q;
            g_Q[bl*DD + t] = q;
        }
        __syncthreads();
        for (int o = t; o < 3*DD; o += 128) {
            const float* src = (o < DD) ? Qs : xr;
            const float4* w4 = (const float4*)(ipw + ((long)b1*3*DD + o) * DD);
            const float4* s4 = (const float4*)src;
            float acc = 0.f;
            #pragma unroll
            for (int kk = 0; kk < 16; kk++) {
                float4 w = w4[kk], x = s4[kk];
                acc += w.x*x.x + w.y*x.y + w.z*x.z + w.w*x.w;
            }
            acc += ipb[b1*3*DD + o];
            if      (o < DD)   g_q[bl*DD + o      ] = acc;
            else if (o < 2*DD) g_k[bl*DD + o - 64 ] = acc;
            else               g_v[bl*DD + o - 128] = acc;
        }
        return;
    }

    if (t < DD) {
        float lf = (xr[t] - mv[0]) * mv[1] * lls[t] + llb[t];
        part[t]      = lf * E[(long)pos[bl]*DD + t];
        part[t + 64] = lf * E[(long)neg[bl]*DD + t];
    }
    __syncthreads();
    if (t < 32) {
        float s = part[t] + part[t+32];
        #pragma unroll
        for (int o = 16; o; o >>= 1) s += __shfl_xor_sync(0xffffffffu, s, o);
        if (t == 0) out[bl] = s;
    } else if (t < 64) {
        int tn = t - 32;
        float s = part[64 + tn] + part[96 + tn];
        #pragma unroll
        for (int o = 16; o; o >>= 1) s += __shfl_xor_sync(0xffffffffu, s, o);
        if (tn == 0) out[BL + bl] = s;
    }
}

// ---------------- launch ------------------------------------------------------
extern "C" void kernel_launch(void* const* d_in, const int* in_sizes, int n_in,
                              void* d_out, int out_size)
{
    const float* uemb = (const float*)d_in[0];
    const float* E    = (const float*)d_in[1];
    const float* rel  = (const float*)d_in[2];
    const float* Wt   = (const float*)d_in[3];
    const float* W1   = (const float*)d_in[4];
    const float* W2   = (const float*)d_in[5];
    const float* pemb = (const float*)d_in[6];
    const float* lnas = (const float*)d_in[7];
    const float* lnab = (const float*)d_in[8];
    const float* ipw  = (const float*)d_in[9];
    const float* ipb  = (const float*)d_in[10];
    const float* opw  = (const float*)d_in[11];
    const float* opb  = (const float*)d_in[12];
    const float* fs   = (const float*)d_in[13];
    const float* fb   = (const float*)d_in[14];
    const float* c1w  = (const float*)d_in[15];
    const float* c1b  = (const float*)d_in[16];
    const float* c2w  = (const float*)d_in[17];
    const float* c2b  = (const float*)d_in[18];
    const float* lls  = (const float*)d_in[19];
    const float* llb  = (const float*)d_in[20];
    const int*   user = (const int*)d_in[21];
    const int*   seq  = (const int*)d_in[22];
    const int*   pos  = (const int*)d_in[23];
    const int*   neg  = (const int*)d_in[24];
    const int*   mh   = (const int*)d_in[25];
    const int*   mr   = (const int*)d_in[26];
    const int*   mt   = (const int*)d_in[27];
    float* out = (float*)d_out;

    for (int hop = 0; hop < NHOP; hop++) {
        kv_rip<<<320, 256>>>(rel, E, seq, hop);
        kh_rip<<<BL, 256>>>(E, Wt, mh, mr, mt, seq, hop, hop == NHOP - 1);
    }
    ks2_rip<<<BB, 256>>>(W1, W2, uemb, user, pemb, E, seq,
                         lnas, lnab, ipw, ipb);
    for (int bb = 0; bb < NBLK; bb++) {
        ka_rip<<<BB*HH*2, 256>>>();
        km_rip<<<BL, 128>>>(opw, opb, fs, fb, c1w, c1b, c2w, c2b, bb,
                            bb == NBLK - 1, E, lls, llb, pos, neg, out,
                            lnas, lnab, ipw, ipb);
    }
}

// round 11
// speedup vs baseline: 1.7165x; 1.7165x over previous
#include <cuda_runtime.h>
#include <cuda_bf16.h>
#include <cstdint>

#define BB   8
#define LL   50
#define BL   400
#define MM   32
#define NHOP 2
#define DD   64
#define HH   2
#define HDD  32
#define RR   20
#define NBLK 2

// ---------------- scratch ----------------------------------------------------
__device__ float g_item [BL*DD];
__device__ float g_osum [BL*DD];
__device__ float g_V    [BL*RR*DD];
__device__ float g_x    [BL*DD];
__device__ float g_Q    [BL*DD];
__device__ float g_q    [BL*DD];
__device__ float g_k    [BL*DD];
__device__ float g_v    [BL*DD];
__device__ float g_ctx  [BL*DD];

__device__ __forceinline__ float lrelu(float x) { return x > 0.f ? x : 0.01f * x; }

__device__ __forceinline__ void pdl_trigger() {
#if defined(__CUDA_ARCH__) && __CUDA_ARCH__ >= 900
    cudaTriggerProgrammaticLaunchCompletion();
#endif
}
__device__ __forceinline__ void pdl_wait() {
#if defined(__CUDA_ARCH__) && __CUDA_ARCH__ >= 900
    cudaGridDependencySynchronize();
#endif
}

// ---------------- V[bl,r,j] = sum_i item[bl,i] * R_r[i,j] --------------------
__global__ __launch_bounds__(256) void kv_rip(
    const float* __restrict__ rel, const float* __restrict__ E,
    const int* __restrict__ seq, int hop)
{
    __shared__ __align__(16) float IT[25*DD];
    pdl_trigger();
    const int u = blockIdx.x;
    const int r = u >> 4, c = u & 15;
    const int t = threadIdx.x;
    const int j = t & 63, gg = t >> 6;

    // external prefetch: R column (overlaps predecessor kernel)
    float Rj[64];
    const float* Rr = rel + (long)r*4096 + j;
    #pragma unroll
    for (int i = 0; i < 64; i++) Rj[i] = Rr[i*64];

    pdl_wait();   // g_item (hop 1) produced by previous kh

    const int base = c * 25;
    for (int idx = t; idx < 25*DD; idx += 256) {
        int bl = base + (idx >> 6), d = idx & 63;
        IT[idx] = hop ? g_item[bl*DD + d] : E[(long)seq[bl]*DD + d];
    }
    __syncthreads();

    for (int l = gg; l < 25; l += 4) {
        const float4* it4 = (const float4*)(IT + l*DD);
        float a0 = 0.f, a1 = 0.f, a2 = 0.f, a3 = 0.f;
        #pragma unroll
        for (int k2 = 0; k2 < 4; k2++) {
            float4 x0 = it4[k2], x1 = it4[k2+4], x2 = it4[k2+8], x3 = it4[k2+12];
            a0 += x0.x*Rj[4*k2   ] + x0.y*Rj[4*k2+1 ] + x0.z*Rj[4*k2+2 ] + x0.w*Rj[4*k2+3 ];
            a1 += x1.x*Rj[4*k2+16] + x1.y*Rj[4*k2+17] + x1.z*Rj[4*k2+18] + x1.w*Rj[4*k2+19];
            a2 += x2.x*Rj[4*k2+32] + x2.y*Rj[4*k2+33] + x2.z*Rj[4*k2+34] + x2.w*Rj[4*k2+35];
            a3 += x3.x*Rj[4*k2+48] + x3.y*Rj[4*k2+49] + x3.z*Rj[4*k2+50] + x3.w*Rj[4*k2+51];
        }
        g_V[((long)(base + l)*RR + r)*DD + j] = (a0 + a1) + (a2 + a3);
    }
}

// ---------------- per-(b,l) hop update (256 threads) -------------------------
__global__ __launch_bounds__(256) void kh_rip(
    const float* __restrict__ E, const float* __restrict__ Wt,
    const int* __restrict__ mh, const int* __restrict__ mr, const int* __restrict__ mt,
    const int* __restrict__ seq, int hop, int last)
{
    __shared__ float sc[MM], pr[MM], u[DD], part[256], item_s[DD];
    pdl_trigger();
    const int bl = blockIdx.x, t = threadIdx.x;
    const int d = t & 63, quarter = t >> 6;
    const int mbase = (bl*NHOP + hop) * MM;

    // ---- external prefetches (overlap kv execution) ----
    const int m = t >> 3, e8 = t & 7;
    const int hid = mh[mbase + m], rid = mr[mbase + m];
    const float4* Hh = (const float4*)(E + (long)hid * DD) + e8*2;
    float4 ha0 = Hh[0], ha1 = Hh[1];

    float treg[8];
    const int* mtb = mt + mbase + quarter*8;
    #pragma unroll
    for (int m2 = 0; m2 < 8; m2++)
        treg[m2] = E[(long)mtb[m2]*DD + d];

    if (!hop && t < DD)
        item_s[t] = E[(long)seq[bl]*DD + t];

    pdl_wait();   // g_V (and g_item for hop 1) now visible

    if (hop && t < DD)
        item_s[t] = g_item[bl*DD + t];

    const float4* Vv = (const float4*)(g_V + ((long)bl*RR + rid) * DD) + e8*2;
    float4 va0 = Vv[0], va1 = Vv[1];

    float acc = va0.x*ha0.x + va0.y*ha0.y + va0.z*ha0.z + va0.w*ha0.w
              + va1.x*ha1.x + va1.y*ha1.y + va1.z*ha1.z + va1.w*ha1.w;
    acc += __shfl_down_sync(0xffffffffu, acc, 4, 8);
    acc += __shfl_down_sync(0xffffffffu, acc, 2, 8);
    acc += __shfl_down_sync(0xffffffffu, acc, 1, 8);
    if (e8 == 0) sc[m] = acc;
    __syncthreads();

    if (t < 32) {
        float v = sc[t];
        float mx = v;
        #pragma unroll
        for (int o = 16; o; o >>= 1) mx = fmaxf(mx, __shfl_xor_sync(0xffffffffu, mx, o));
        float e = __expf(v - mx);
        float s = e;
        #pragma unroll
        for (int o = 16; o; o >>= 1) s += __shfl_xor_sync(0xffffffffu, s, o);
        pr[t] = e / s;
    }
    __syncthreads();

    float od = 0.f;
    #pragma unroll
    for (int m2 = 0; m2 < 8; m2++)
        od += pr[quarter*8 + m2] * treg[m2];
    part[t] = od;
    __syncthreads();
    if (t < DD) {
        float o = part[t] + part[t + 64] + part[t + 128] + part[t + 192];
        if (hop == 0) g_osum[bl*DD + t] = o;
        else          g_osum[bl*DD + t] += o;
        u[t] = o + item_s[t];
    }
    __syncthreads();

    if (!last) {
        const float4* wr = (const float4*)(Wt + d*DD) + quarter*4;
        const float4* uu = (const float4*)u + quarter*4;
        float a = 0.f;
        #pragma unroll
        for (int kk = 0; kk < 4; kk++) {
            float4 w = wr[kk], x = uu[kk];
            a += w.x*x.x + w.y*x.y + w.z*x.z + w.w*x.w;
        }
        part[t] = a;
        __syncthreads();
        if (t < DD)
            g_item[bl*DD + t] = lrelu(part[t] + part[t+64] + part[t+128] + part[t+192]);
    }
}

// ---------------- sequential interest scan (per batch b) ---------------------
__global__ __launch_bounds__(128) void ks_rip(
    const float* __restrict__ W1, const float* __restrict__ W2,
    const float* __restrict__ uemb, const int* __restrict__ user,
    const float* __restrict__ pemb, const float* __restrict__ E,
    const int* __restrict__ seq)
{
    __shared__ float S[LL*DD];
    __shared__ float AB[128];
    __shared__ float T[128];
    pdl_trigger();
    const int b = blockIdx.x, t = threadIdx.x;
    const int i = t & 63, path = t >> 6;

    // external prefetch: weights + user embedding
    const float* W = path ? W2 : W1;
    const float4* wr = (const float4*)(W + i*DD);
    float4 wv[16];
    #pragma unroll
    for (int kk = 0; kk < 16; kk++) wv[kk] = wr[kk];
    float c = uemb[(long)user[b] * DD + i];

    pdl_wait();   // g_osum produced by kh

    for (int idx = t; idx < LL*DD; idx += 128) {
        int l = idx >> 6, d = idx & 63;
        S[idx] = E[(long)seq[b*LL + l]*DD + d] + g_osum[b*LL*DD + idx];
    }
    __syncthreads();

    for (int st = 0; st < LL; st++) {
        float sv = S[st*DD + i];
        AB[path*64 + i] = path ? (sv * c) : (sv + c);
        __syncthreads();
        const float4* in = (const float4*)(AB + path*64);
        float a0 = 0.f, a1 = 0.f, a2 = 0.f, a3 = 0.f;
        #pragma unroll
        for (int kk = 0; kk < 16; kk += 4) {
            float4 x0 = in[kk],   x1 = in[kk+1], x2 = in[kk+2], x3 = in[kk+3];
            a0 += wv[kk  ].x*x0.x + wv[kk  ].y*x0.y + wv[kk  ].z*x0.z + wv[kk  ].w*x0.w;
            a1 += wv[kk+1].x*x1.x + wv[kk+1].y*x1.y + wv[kk+1].z*x1.z + wv[kk+1].w*x1.w;
            a2 += wv[kk+2].x*x2.x + wv[kk+2].y*x2.y + wv[kk+2].z*x2.z + wv[kk+2].w*x2.w;
            a3 += wv[kk+3].x*x3.x + wv[kk+3].y*x3.y + wv[kk+3].z*x3.z + wv[kk+3].w*x3.w;
        }
        float r = lrelu((a0 + a1) + (a2 + a3));
        T[path*64 + i] = r;
        __syncthreads();
        float out = T[i] + T[64 + i];
        c = out;
        if (path == 0)
            g_x[(b*LL + st)*DD + i] = out * 8.0f + pemb[st*DD + i];
    }
}

// ---------------- per-row LN -> Q, then q/k/v projections (bb=0) -------------
__global__ __launch_bounds__(128) void kq_rip(
    const float* __restrict__ lns, const float* __restrict__ lnb,
    const float* __restrict__ ipw, const float* __restrict__ ipb, int bb)
{
    __shared__ float xs[DD], Qs[DD];
    __shared__ float mv[2];
    pdl_trigger();
    const int bl = blockIdx.x, t = threadIdx.x;
    pdl_wait();   // g_x produced by ks
    if (t < DD) xs[t] = g_x[bl*DD + t];
    __syncthreads();
    if (t < 32) {
        float s = xs[t] + xs[t + 32];
        #pragma unroll
        for (int o = 16; o; o >>= 1) s += __shfl_xor_sync(0xffffffffu, s, o);
        float mean = s * (1.f/64.f);
        float d0 = xs[t] - mean, d1 = xs[t+32] - mean;
        float vs = d0*d0 + d1*d1;
        #pragma unroll
        for (int o = 16; o; o >>= 1) vs += __shfl_xor_sync(0xffffffffu, vs, o);
        if (t == 0) { mv[0] = mean; mv[1] = rsqrtf(vs * (1.f/64.f) + 1e-8f); }
    }
    __syncthreads();
    if (t < DD) {
        float q = (xs[t] - mv[0]) * mv[1] * lns[bb*DD + t] + lnb[bb*DD + t];
        Qs[t] = q;
        g_Q[bl*DD + t] = q;
    }
    __syncthreads();

    for (int o = t; o < 3*DD; o += 128) {
        const float* src = (o < DD) ? Qs : xs;
        const float4* w4 = (const float4*)(ipw + ((long)bb*3*DD + o) * DD);
        const float4* s4 = (const float4*)src;
        float acc = 0.f;
        #pragma unroll
        for (int kk = 0; kk < 16; kk++) {
            float4 w = w4[kk], x = s4[kk];
            acc += w.x*x.x + w.y*x.y + w.z*x.z + w.w*x.w;
        }
        acc += ipb[bb*3*DD + o];
        if      (o < DD)   g_q[bl*DD + o      ] = acc;
        else if (o < 2*DD) g_k[bl*DD + o - 64 ] = acc;
        else               g_v[bl*DD + o - 128] = acc;
    }
}

// ---------------- causal attention, block = (b,h,qparity) --------------------
__global__ __launch_bounds__(256) void ka_rip()
{
    __shared__ float qh[LL*36], kh[LL*36], vh[LL*36];
    __shared__ float ps[8][52];
    pdl_trigger();
    const int blk = blockIdx.x;
    const int qs = blk & 1, h = (blk >> 1) & 1, b = blk >> 2;
    const int t = threadIdx.x;
    pdl_wait();   // g_q/g_k/g_v produced

    for (int idx = t; idx < LL*HDD; idx += 256) {
        int l = idx >> 5, d = idx & 31;
        int src = (b*LL + l)*DD + h*HDD + d;
        qh[l*36 + d] = g_q[src];
        kh[l*36 + d] = g_k[src];
        vh[l*36 + d] = g_v[src];
    }
    __syncthreads();

    const int w = t >> 5, lane = t & 31;
    const float scl = 0.17677669529663687f;
    for (int qi = 2*w + qs; qi < LL; qi += 16) {
        float4 qreg[8];
        const float4* qa = (const float4*)(qh + qi*36);
        #pragma unroll
        for (int kk = 0; kk < 8; kk++) qreg[kk] = qa[kk];

        int k0 = lane, k1 = lane + 32;
        float s0 = -3.0e38f, s1 = -3.0e38f;
        if (k0 <= qi) {
            const float4* ka = (const float4*)(kh + k0*36);
            float a = 0.f;
            #pragma unroll
            for (int kk = 0; kk < 8; kk++) {
                float4 kv = ka[kk];
                a += qreg[kk].x*kv.x + qreg[kk].y*kv.y + qreg[kk].z*kv.z + qreg[kk].w*kv.w;
            }
            s0 = a * scl;
        }
        if (k1 <= qi) {
            const float4* ka = (const float4*)(kh + k1*36);
            float a = 0.f;
            #pragma unroll
            for (int kk = 0; kk < 8; kk++) {
                float4 kv = ka[kk];
                a += qreg[kk].x*kv.x + qreg[kk].y*kv.y + qreg[kk].z*kv.z + qreg[kk].w*kv.w;
            }
            s1 = a * scl;
        }
        float mx = fmaxf(s0, s1);
        #pragma unroll
        for (int o = 16; o; o >>= 1) mx = fmaxf(mx, __shfl_xor_sync(0xffffffffu, mx, o));
        float e0 = (k0 <= qi) ? __expf(s0 - mx) : 0.f;
        float e1 = (k1 <= qi) ? __expf(s1 - mx) : 0.f;
        float sm = e0 + e1;
        #pragma unroll
        for (int o = 16; o; o >>= 1) sm += __shfl_xor_sync(0xffffffffu, sm, o);
        float inv = 1.f / sm;
        ps[w][k0] = e0 * inv;
        if (k1 < LL) ps[w][k1] = e1 * inv;
        __syncwarp();
        float acc = 0.f;
        for (int kj = 0; kj <= qi; kj++)
            acc += ps[w][kj] * vh[kj*36 + lane];
        g_ctx[(b*LL + qi)*DD + h*HDD + lane] = acc;
        __syncwarp();
    }
}

// ---------------- out-proj + residual + LN + FFN, then NEXT-block qkv or logits
__global__ __launch_bounds__(128) void km_rip(
    const float* __restrict__ opw, const float* __restrict__ opb,
    const float* __restrict__ fs,  const float* __restrict__ fb,
    const float* __restrict__ c1w, const float* __restrict__ c1b,
    const float* __restrict__ c2w, const float* __restrict__ c2b, int bb,
    int last, const float* __restrict__ E,
    const float* __restrict__ lls, const float* __restrict__ llb,
    const int* __restrict__ pos, const int* __restrict__ neg,
    float* __restrict__ out,
    const float* __restrict__ lns, const float* __restrict__ lnb,
    const float* __restrict__ ipw, const float* __restrict__ ipb)
{
    __shared__ float cs[DD], xr[DD], x2[DD], hdn[DD], part[128], Qs[DD];
    __shared__ float mv[2];
    pdl_trigger();
    const int bl = blockIdx.x, t = threadIdx.x;
    const int i = t & 63, half = t >> 6;

    // external prefetch: out-proj weight row slice
    float4 wpre[8];
    {
        const float4* wr = (const float4*)(opw + ((long)bb*DD + i)*DD) + half*8;
        #pragma unroll
        for (int kk = 0; kk < 8; kk++) wpre[kk] = wr[kk];
    }

    pdl_wait();   // g_ctx / g_Q produced

    if (t < DD) cs[t] = g_ctx[bl*DD + t];
    __syncthreads();

    {
        const float4* uu = (const float4*)cs + half*8;
        float a = 0.f;
        #pragma unroll
        for (int kk = 0; kk < 8; kk++) {
            float4 x = uu[kk];
            a += wpre[kk].x*x.x + wpre[kk].y*x.y + wpre[kk].z*x.z + wpre[kk].w*x.w;
        }
        part[t] = a;
    }
    __syncthreads();
    if (t < DD)
        xr[t] = part[t] + part[t+64] + opb[bb*DD + t] + g_Q[bl*DD + t];
    __syncthreads();

    if (t < 32) {
        float s = xr[t] + xr[t+32];
        #pragma unroll
        for (int o = 16; o; o >>= 1) s += __shfl_xor_sync(0xffffffffu, s, o);
        float mean = s * (1.f/64.f);
        float d0 = xr[t]-mean, d1 = xr[t+32]-mean;
        float vs = d0*d0 + d1*d1;
        #pragma unroll
        for (int o = 16; o; o >>= 1) vs += __shfl_xor_sync(0xffffffffu, vs, o);
        if (t == 0) { mv[0] = mean; mv[1] = rsqrtf(vs*(1.f/64.f) + 1e-8f); }
    }
    __syncthreads();
    if (t < DD)
        x2[t] = (xr[t] - mv[0]) * mv[1] * fs[bb*DD + t] + fb[bb*DD + t];
    __syncthreads();

    {
        const float4* wr = (const float4*)(c1w + ((long)bb*DD + i)*DD) + half*8;
        const float4* uu = (const float4*)x2 + half*8;
        float a = 0.f;
        #pragma unroll
        for (int kk = 0; kk < 8; kk++) {
            float4 w = wr[kk], x = uu[kk];
            a += w.x*x.x + w.y*x.y + w.z*x.z + w.w*x.w;
        }
        part[t] = a;
    }
    __syncthreads();
    if (t < DD) {
        float v = part[t] + part[t+64] + c1b[bb*DD + t];
        hdn[t] = v > 0.f ? v : 0.f;
    }
    __syncthreads();

    {
        const float4* wr = (const float4*)(c2w + ((long)bb*DD + i)*DD) + half*8;
        const float4* uu = (const float4*)hdn + half*8;
        float a = 0.f;
        #pragma unroll
        for (int kk = 0; kk < 8; kk++) {
            float4 w = wr[kk], x = uu[kk];
            a += w.x*x.x + w.y*x.y + w.z*x.z + w.w*x.w;
        }
        part[t] = a;
    }
    __syncthreads();
    if (t < DD)
        xr[t] = x2[t] + part[t] + part[t+64] + c2b[bb*DD + t];
    __syncthreads();

    if (t < 32) {
        float s = xr[t] + xr[t+32];
        #pragma unroll
        for (int o = 16; o; o >>= 1) s += __shfl_xor_sync(0xffffffffu, s, o);
        float mean = s * (1.f/64.f);
        float d0 = xr[t]-mean, d1 = xr[t+32]-mean;
        float vs = d0*d0 + d1*d1;
        #pragma unroll
        for (int o = 16; o; o >>= 1) vs += __shfl_xor_sync(0xffffffffu, vs, o);
        if (t == 0) { mv[0] = mean; mv[1] = rsqrtf(vs*(1.f/64.f) + 1e-8f); }
    }
    __syncthreads();

    if (!last) {
        const int b1 = bb + 1;
        if (t < DD) {
            float q = (xr[t] - mv[0]) * mv[1] * lns[b1*DD + t] + lnb[b1*DD + t];
            Qs[t] = q;
            g_Q[bl*DD + t] = q;
        }
        __syncthreads();
        for (int o = t; o < 3*DD; o += 128) {
            const float* src = (o < DD) ? Qs : xr;
            const float4* w4 = (const float4*)(ipw + ((long)b1*3*DD + o) * DD);
            const float4* s4 = (const float4*)src;
            float acc = 0.f;
            #pragma unroll
            for (int kk = 0; kk < 16; kk++) {
                float4 w = w4[kk], x = s4[kk];
                acc += w.x*x.x + w.y*x.y + w.z*x.z + w.w*x.w;
            }
            acc += ipb[b1*3*DD + o];
            if      (o < DD)   g_q[bl*DD + o      ] = acc;
            else if (o < 2*DD) g_k[bl*DD + o - 64 ] = acc;
            else               g_v[bl*DD + o - 128] = acc;
        }
        return;
    }

    if (t < DD) {
        float lf = (xr[t] - mv[0]) * mv[1] * lls[t] + llb[t];
        part[t]      = lf * E[(long)pos[bl]*DD + t];
        part[t + 64] = lf * E[(long)neg[bl]*DD + t];
    }
    __syncthreads();
    if (t < 32) {
        float s = part[t] + part[t+32];
        #pragma unroll
        for (int o = 16; o; o >>= 1) s += __shfl_xor_sync(0xffffffffu, s, o);
        if (t == 0) out[bl] = s;
    } else if (t < 64) {
        int tn = t - 32;
        float s = part[64 + tn] + part[96 + tn];
        #pragma unroll
        for (int o = 16; o; o >>= 1) s += __shfl_xor_sync(0xffffffffu, s, o);
        if (tn == 0) out[BL + bl] = s;
    }
}

// ---------------- PDL launch helper ------------------------------------------
template <typename F, typename... Args>
static void launch_pdl(F kern, dim3 grid, dim3 block, Args... args)
{
    cudaLaunchConfig_t cfg = {};
    cfg.gridDim = grid;
    cfg.blockDim = block;
    cfg.dynamicSmemBytes = 0;
    cfg.stream = 0;
    cudaLaunchAttribute at[1];
    at[0].id = cudaLaunchAttributeProgrammaticStreamSerialization;
    at[0].val.programmaticStreamSerializationAllowed = 1;
    cfg.attrs = at;
    cfg.numAttrs = 1;
    cudaLaunchKernelEx(&cfg, kern, args...);
}

// ---------------- launch ------------------------------------------------------
extern "C" void kernel_launch(void* const* d_in, const int* in_sizes, int n_in,
                              void* d_out, int out_size)
{
    const float* uemb = (const float*)d_in[0];
    const float* E    = (const float*)d_in[1];
    const float* rel  = (const float*)d_in[2];
    const float* Wt   = (const float*)d_in[3];
    const float* W1   = (const float*)d_in[4];
    const float* W2   = (const float*)d_in[5];
    const float* pemb = (const float*)d_in[6];
    const float* lnas = (const float*)d_in[7];
    const float* lnab = (const float*)d_in[8];
    const float* ipw  = (const float*)d_in[9];
    const float* ipb  = (const float*)d_in[10];
    const float* opw  = (const float*)d_in[11];
    const float* opb  = (const float*)d_in[12];
    const float* fs   = (const float*)d_in[13];
    const float* fb   = (const float*)d_in[14];
    const float* c1w  = (const float*)d_in[15];
    const float* c1b  = (const float*)d_in[16];
    const float* c2w  = (const float*)d_in[17];
    const float* c2b  = (const float*)d_in[18];
    const float* lls  = (const float*)d_in[19];
    const float* llb  = (const float*)d_in[20];
    const int*   user = (const int*)d_in[21];
    const int*   seq  = (const int*)d_in[22];
    const int*   pos  = (const int*)d_in[23];
    const int*   neg  = (const int*)d_in[24];
    const int*   mh   = (const int*)d_in[25];
    const int*   mr   = (const int*)d_in[26];
    const int*   mt   = (const int*)d_in[27];
    float* out = (float*)d_out;

    for (int hop = 0; hop < NHOP; hop++) {
        launch_pdl(kv_rip, dim3(320), dim3(256), rel, E, seq, hop);
        launch_pdl(kh_rip, dim3(BL), dim3(256), E, Wt, mh, mr, mt, seq,
                   hop, (int)(hop == NHOP - 1));
    }
    launch_pdl(ks_rip, dim3(BB), dim3(128), W1, W2, uemb, user, pemb, E, seq);
    launch_pdl(kq_rip, dim3(BL), dim3(128), lnas, lnab, ipw, ipb, 0);
    for (int bb = 0; bb < NBLK; bb++) {
        launch_pdl(ka_rip, dim3(BB*HH*2), dim3(256));
        launch_pdl(km_rip, dim3(BL), dim3(128), opw, opb, fs, fb, c1w, c1b,
                   c2w, c2b, bb, (int)(bb == NBLK - 1), E, lls, llb, pos, neg,
                   out, lnas, lnab, ipw, ipb);
    }
}

// round 12
// speedup vs baseline: 2.0418x; 1.1895x over previous
#include <cuda_runtime.h>
#include <cuda_bf16.h>
#include <cstdint>

#define BB   8
#define LL   50
#define BL   400
#define MM   32
#define NHOP 2
#define DD   64
#define HH   2
#define HDD  32
#define RR   20
#define NBLK 2

// ---------------- scratch ----------------------------------------------------
__device__ float g_item [BL*DD];
__device__ float g_osum [BL*DD];
__device__ float g_V    [BL*RR*DD];
__device__ float g_x    [BL*DD];
__device__ float g_Q    [BL*DD];
__device__ float g_q    [BL*DD];
__device__ float g_k    [BL*DD];
__device__ float g_v    [BL*DD];

__device__ __forceinline__ float lrelu(float x) { return x > 0.f ? x : 0.01f * x; }

// ---------------- V[bl,r,j] = sum_i item[bl,i] * R_r[i,j] --------------------
__global__ __launch_bounds__(256) void kv_rip(
    const float* __restrict__ rel, const float* __restrict__ E,
    const int* __restrict__ seq, int hop)
{
    __shared__ __align__(16) float IT[25*DD];
    const int u = blockIdx.x;
    const int r = u >> 4, c = u & 15;
    const int t = threadIdx.x;
    const int j = t & 63, gg = t >> 6;

    float Rj[64];
    const float* Rr = rel + (long)r*4096 + j;
    #pragma unroll
    for (int i = 0; i < 64; i++) Rj[i] = Rr[i*64];

    const int base = c * 25;
    for (int idx = t; idx < 25*DD; idx += 256) {
        int bl = base + (idx >> 6), d = idx & 63;
        IT[idx] = hop ? g_item[bl*DD + d] : E[(long)seq[bl]*DD + d];
    }
    __syncthreads();

    for (int l = gg; l < 25; l += 4) {
        const float4* it4 = (const float4*)(IT + l*DD);
        float a0 = 0.f, a1 = 0.f, a2 = 0.f, a3 = 0.f;
        #pragma unroll
        for (int k2 = 0; k2 < 4; k2++) {
            float4 x0 = it4[k2], x1 = it4[k2+4], x2 = it4[k2+8], x3 = it4[k2+12];
            a0 += x0.x*Rj[4*k2   ] + x0.y*Rj[4*k2+1 ] + x0.z*Rj[4*k2+2 ] + x0.w*Rj[4*k2+3 ];
            a1 += x1.x*Rj[4*k2+16] + x1.y*Rj[4*k2+17] + x1.z*Rj[4*k2+18] + x1.w*Rj[4*k2+19];
            a2 += x2.x*Rj[4*k2+32] + x2.y*Rj[4*k2+33] + x2.z*Rj[4*k2+34] + x2.w*Rj[4*k2+35];
            a3 += x3.x*Rj[4*k2+48] + x3.y*Rj[4*k2+49] + x3.z*Rj[4*k2+50] + x3.w*Rj[4*k2+51];
        }
        g_V[((long)(base + l)*RR + r)*DD + j] = (a0 + a1) + (a2 + a3);
    }
}

// ---------------- per-(b,l) hop update (256 threads) -------------------------
__global__ __launch_bounds__(256) void kh_rip(
    const float* __restrict__ E, const float* __restrict__ Wt,
    const int* __restrict__ mh, const int* __restrict__ mr, const int* __restrict__ mt,
    const int* __restrict__ seq, int hop, int last)
{
    __shared__ float sc[MM], pr[MM], u[DD], part[256], item_s[DD];
    const int bl = blockIdx.x, t = threadIdx.x;
    const int d = t & 63, quarter = t >> 6;
    const int mbase = (bl*NHOP + hop) * MM;

    if (t < DD)
        item_s[t] = hop ? g_item[bl*DD + t] : E[(long)seq[bl]*DD + t];

    const int m = t >> 3, e8 = t & 7;
    const int hid = mh[mbase + m], rid = mr[mbase + m];
    const float4* Vv = (const float4*)(g_V + ((long)bl*RR + rid) * DD) + e8*2;
    const float4* Hh = (const float4*)(E + (long)hid * DD) + e8*2;
    float4 va0 = Vv[0], va1 = Vv[1], ha0 = Hh[0], ha1 = Hh[1];

    float treg[8];
    const int* mtb = mt + mbase + quarter*8;
    #pragma unroll
    for (int m2 = 0; m2 < 8; m2++)
        treg[m2] = E[(long)mtb[m2]*DD + d];

    float acc = va0.x*ha0.x + va0.y*ha0.y + va0.z*ha0.z + va0.w*ha0.w
              + va1.x*ha1.x + va1.y*ha1.y + va1.z*ha1.z + va1.w*ha1.w;
    acc += __shfl_down_sync(0xffffffffu, acc, 4, 8);
    acc += __shfl_down_sync(0xffffffffu, acc, 2, 8);
    acc += __shfl_down_sync(0xffffffffu, acc, 1, 8);
    if (e8 == 0) sc[m] = acc;
    __syncthreads();

    if (t < 32) {
        float v = sc[t];
        float mx = v;
        #pragma unroll
        for (int o = 16; o; o >>= 1) mx = fmaxf(mx, __shfl_xor_sync(0xffffffffu, mx, o));
        float e = __expf(v - mx);
        float s = e;
        #pragma unroll
        for (int o = 16; o; o >>= 1) s += __shfl_xor_sync(0xffffffffu, s, o);
        pr[t] = e / s;
    }
    __syncthreads();

    float od = 0.f;
    #pragma unroll
    for (int m2 = 0; m2 < 8; m2++)
        od += pr[quarter*8 + m2] * treg[m2];
    part[t] = od;
    __syncthreads();
    if (t < DD) {
        float o = part[t] + part[t + 64] + part[t + 128] + part[t + 192];
        if (hop == 0) g_osum[bl*DD + t] = o;
        else          g_osum[bl*DD + t] += o;
        u[t] = o + item_s[t];
    }
    __syncthreads();

    if (!last) {
        const float4* wr = (const float4*)(Wt + d*DD) + quarter*4;
        const float4* uu = (const float4*)u + quarter*4;
        float a = 0.f;
        #pragma unroll
        for (int kk = 0; kk < 4; kk++) {
            float4 w = wr[kk], x = uu[kk];
            a += w.x*x.x + w.y*x.y + w.z*x.z + w.w*x.w;
        }
        part[t] = a;
        __syncthreads();
        if (t < DD)
            g_item[bl*DD + t] = lrelu(part[t] + part[t+64] + part[t+128] + part[t+192]);
    }
}

// ---------------- sequential interest scan (per batch b) ---------------------
__global__ __launch_bounds__(128) void ks_rip(
    const float* __restrict__ W1, const float* __restrict__ W2,
    const float* __restrict__ uemb, const int* __restrict__ user,
    const float* __restrict__ pemb, const float* __restrict__ E,
    const int* __restrict__ seq)
{
    __shared__ float S[LL*DD];
    __shared__ float AB[128];
    __shared__ float T[128];
    const int b = blockIdx.x, t = threadIdx.x;
    const int i = t & 63, path = t >> 6;

    const float* W = path ? W2 : W1;
    const float4* wr = (const float4*)(W + i*DD);
    float4 wv[16];
    #pragma unroll
    for (int kk = 0; kk < 16; kk++) wv[kk] = wr[kk];

    for (int idx = t; idx < LL*DD; idx += 128) {
        int l = idx >> 6, d = idx & 63;
        S[idx] = E[(long)seq[b*LL + l]*DD + d] + g_osum[b*LL*DD + idx];
    }

    float c = uemb[(long)user[b] * DD + i];
    __syncthreads();

    for (int st = 0; st < LL; st++) {
        float sv = S[st*DD + i];
        AB[path*64 + i] = path ? (sv * c) : (sv + c);
        __syncthreads();
        const float4* in = (const float4*)(AB + path*64);
        float a0 = 0.f, a1 = 0.f, a2 = 0.f, a3 = 0.f;
        #pragma unroll
        for (int kk = 0; kk < 16; kk += 4) {
            float4 x0 = in[kk],   x1 = in[kk+1], x2 = in[kk+2], x3 = in[kk+3];
            a0 += wv[kk  ].x*x0.x + wv[kk  ].y*x0.y + wv[kk  ].z*x0.z + wv[kk  ].w*x0.w;
            a1 += wv[kk+1].x*x1.x + wv[kk+1].y*x1.y + wv[kk+1].z*x1.z + wv[kk+1].w*x1.w;
            a2 += wv[kk+2].x*x2.x + wv[kk+2].y*x2.y + wv[kk+2].z*x2.z + wv[kk+2].w*x2.w;
            a3 += wv[kk+3].x*x3.x + wv[kk+3].y*x3.y + wv[kk+3].z*x3.z + wv[kk+3].w*x3.w;
        }
        float r = lrelu((a0 + a1) + (a2 + a3));
        T[path*64 + i] = r;
        __syncthreads();
        float out = T[i] + T[64 + i];
        c = out;
        if (path == 0)
            g_x[(b*LL + st)*DD + i] = out * 8.0f + pemb[st*DD + i];
    }
}

// ---------------- per-row LN -> Q, then q/k/v projections (bb=0) -------------
__global__ __launch_bounds__(128) void kq_rip(
    const float* __restrict__ lns, const float* __restrict__ lnb,
    const float* __restrict__ ipw, const float* __restrict__ ipb, int bb)
{
    __shared__ float xs[DD], Qs[DD];
    __shared__ float mv[2];
    const int bl = blockIdx.x, t = threadIdx.x;
    if (t < DD) xs[t] = g_x[bl*DD + t];
    __syncthreads();
    if (t < 32) {
        float s = xs[t] + xs[t + 32];
        #pragma unroll
        for (int o = 16; o; o >>= 1) s += __shfl_xor_sync(0xffffffffu, s, o);
        float mean = s * (1.f/64.f);
        float d0 = xs[t] - mean, d1 = xs[t+32] - mean;
        float vs = d0*d0 + d1*d1;
        #pragma unroll
        for (int o = 16; o; o >>= 1) vs += __shfl_xor_sync(0xffffffffu, vs, o);
        if (t == 0) { mv[0] = mean; mv[1] = rsqrtf(vs * (1.f/64.f) + 1e-8f); }
    }
    __syncthreads();
    if (t < DD) {
        float q = (xs[t] - mv[0]) * mv[1] * lns[bb*DD + t] + lnb[bb*DD + t];
        Qs[t] = q;
        g_Q[bl*DD + t] = q;
    }
    __syncthreads();

    for (int o = t; o < 3*DD; o += 128) {
        const float* src = (o < DD) ? Qs : xs;
        const float4* w4 = (const float4*)(ipw + ((long)bb*3*DD + o) * DD);
        const float4* s4 = (const float4*)src;
        float acc = 0.f;
        #pragma unroll
        for (int kk = 0; kk < 16; kk++) {
            float4 w = w4[kk], x = s4[kk];
            acc += w.x*x.x + w.y*x.y + w.z*x.z + w.w*x.w;
        }
        acc += ipb[bb*3*DD + o];
        if      (o < DD)   g_q[bl*DD + o      ] = acc;
        else if (o < 2*DD) g_k[bl*DD + o - 64 ] = acc;
        else               g_v[bl*DD + o - 128] = acc;
    }
}

// ---------------- fused attention + out-proj + LN + FFN + next-qkv/logits ----
// block = (b,l), 128 threads. Own-row attention from g_q/g_k/g_v.
__global__ __launch_bounds__(128) void kam_rip(
    const float* __restrict__ opw, const float* __restrict__ opb,
    const float* __restrict__ fs,  const float* __restrict__ fb,
    const float* __restrict__ c1w, const float* __restrict__ c1b,
    const float* __restrict__ c2w, const float* __restrict__ c2b, int bb,
    int last, const float* __restrict__ E,
    const float* __restrict__ lls, const float* __restrict__ llb,
    const int* __restrict__ pos, const int* __restrict__ neg,
    float* __restrict__ out,
    const float* __restrict__ lns, const float* __restrict__ lnb,
    const float* __restrict__ ipw, const float* __restrict__ ipb)
{
    __shared__ float Kh[2][LL*36], Vh[2][LL*36];
    __shared__ float qrow[DD];
    __shared__ float ps[2][52];
    __shared__ float cs[DD], xr[DD], x2[DD], hdn[DD], part[128], Qs[DD];
    __shared__ float mv[2];
    const int bl = blockIdx.x, t = threadIdx.x;
    const int b = bl / LL, l = bl % LL;
    const int i = t & 63, half = t >> 6;
    const int w = t >> 5, lane = t & 31;

    // load K/V (both heads) + q row
    for (int idx = t; idx < LL*HDD*2; idx += 128) {
        int h = (idx >= LL*HDD) ? 1 : 0;
        int r2 = idx - h*LL*HDD;
        int kl = r2 >> 5, d = r2 & 31;
        int src = (b*LL + kl)*DD + h*HDD + d;
        Kh[h][kl*36 + d] = g_k[src];
        Vh[h][kl*36 + d] = g_v[src];
    }
    if (t < DD) qrow[t] = g_q[bl*DD + t];
    __syncthreads();

    // scores + softmax: warp 0 = head 0, warp 1 = head 1
    if (w < 2) {
        const int h = w;
        float4 qreg[8];
        const float4* qa = (const float4*)(qrow + h*HDD);
        #pragma unroll
        for (int kk = 0; kk < 8; kk++) qreg[kk] = qa[kk];
        const float scl = 0.17677669529663687f;

        int k0 = lane, k1 = lane + 32;
        float s0 = -3.0e38f, s1 = -3.0e38f;
        if (k0 <= l) {
            const float4* ka = (const float4*)(Kh[h] + k0*36);
            float a = 0.f;
            #pragma unroll
            for (int kk = 0; kk < 8; kk++) {
                float4 kv = ka[kk];
                a += qreg[kk].x*kv.x + qreg[kk].y*kv.y + qreg[kk].z*kv.z + qreg[kk].w*kv.w;
            }
            s0 = a * scl;
        }
        if (k1 <= l && k1 < LL) {
            const float4* ka = (const float4*)(Kh[h] + k1*36);
            float a = 0.f;
            #pragma unroll
            for (int kk = 0; kk < 8; kk++) {
                float4 kv = ka[kk];
                a += qreg[kk].x*kv.x + qreg[kk].y*kv.y + qreg[kk].z*kv.z + qreg[kk].w*kv.w;
            }
            s1 = a * scl;
        }
        float mx = fmaxf(s0, s1);
        #pragma unroll
        for (int o = 16; o; o >>= 1) mx = fmaxf(mx, __shfl_xor_sync(0xffffffffu, mx, o));
        float e0 = (k0 <= l) ? __expf(s0 - mx) : 0.f;
        float e1 = (k1 <= l && k1 < LL) ? __expf(s1 - mx) : 0.f;
        float sm = e0 + e1;
        #pragma unroll
        for (int o = 16; o; o >>= 1) sm += __shfl_xor_sync(0xffffffffu, sm, o);
        float inv = 1.f / sm;
        ps[w][k0] = e0 * inv;
        if (k1 < LL) ps[w][k1] = e1 * inv;
    }
    __syncthreads();

    // ctx -> cs
    if (t < DD) {
        const int h = t >> 5, d = t & 31;
        float acc = 0.f;
        for (int kj = 0; kj <= l; kj++)
            acc += ps[h][kj] * Vh[h][kj*36 + d];
        cs[t] = acc;
    }
    __syncthreads();

    // out-proj + residual
    {
        const float4* wr = (const float4*)(opw + ((long)bb*DD + i)*DD) + half*8;
        const float4* uu = (const float4*)cs + half*8;
        float a = 0.f;
        #pragma unroll
        for (int kk = 0; kk < 8; kk++) {
            float4 ww = wr[kk], x = uu[kk];
            a += ww.x*x.x + ww.y*x.y + ww.z*x.z + ww.w*x.w;
        }
        part[t] = a;
    }
    __syncthreads();
    if (t < DD)
        xr[t] = part[t] + part[t+64] + opb[bb*DD + t] + g_Q[bl*DD + t];
    __syncthreads();

    if (t < 32) {
        float s = xr[t] + xr[t+32];
        #pragma unroll
        for (int o = 16; o; o >>= 1) s += __shfl_xor_sync(0xffffffffu, s, o);
        float mean = s * (1.f/64.f);
        float d0 = xr[t]-mean, d1 = xr[t+32]-mean;
        float vs = d0*d0 + d1*d1;
        #pragma unroll
        for (int o = 16; o; o >>= 1) vs += __shfl_xor_sync(0xffffffffu, vs, o);
        if (t == 0) { mv[0] = mean; mv[1] = rsqrtf(vs*(1.f/64.f) + 1e-8f); }
    }
    __syncthreads();
    if (t < DD)
        x2[t] = (xr[t] - mv[0]) * mv[1] * fs[bb*DD + t] + fb[bb*DD + t];
    __syncthreads();

    {
        const float4* wr = (const float4*)(c1w + ((long)bb*DD + i)*DD) + half*8;
        const float4* uu = (const float4*)x2 + half*8;
        float a = 0.f;
        #pragma unroll
        for (int kk = 0; kk < 8; kk++) {
            float4 ww = wr[kk], x = uu[kk];
            a += ww.x*x.x + ww.y*x.y + ww.z*x.z + ww.w*x.w;
        }
        part[t] = a;
    }
    __syncthreads();
    if (t < DD) {
        float v = part[t] + part[t+64] + c1b[bb*DD + t];
        hdn[t] = v > 0.f ? v : 0.f;
    }
    __syncthreads();

    {
        const float4* wr = (const float4*)(c2w + ((long)bb*DD + i)*DD) + half*8;
        const float4* uu = (const float4*)hdn + half*8;
        float a = 0.f;
        #pragma unroll
        for (int kk = 0; kk < 8; kk++) {
            float4 ww = wr[kk], x = uu[kk];
            a += ww.x*x.x + ww.y*x.y + ww.z*x.z + ww.w*x.w;
        }
        part[t] = a;
    }
    __syncthreads();
    if (t < DD)
        xr[t] = x2[t] + part[t] + part[t+64] + c2b[bb*DD + t];
    __syncthreads();

    if (t < 32) {
        float s = xr[t] + xr[t+32];
        #pragma unroll
        for (int o = 16; o; o >>= 1) s += __shfl_xor_sync(0xffffffffu, s, o);
        float mean = s * (1.f/64.f);
        float d0 = xr[t]-mean, d1 = xr[t+32]-mean;
        float vs = d0*d0 + d1*d1;
        #pragma unroll
        for (int o = 16; o; o >>= 1) vs += __shfl_xor_sync(0xffffffffu, vs, o);
        if (t == 0) { mv[0] = mean; mv[1] = rsqrtf(vs*(1.f/64.f) + 1e-8f); }
    }
    __syncthreads();

    if (!last) {
        const int b1 = bb + 1;
        if (t < DD) {
            float q = (xr[t] - mv[0]) * mv[1] * lns[b1*DD + t] + lnb[b1*DD + t];
            Qs[t] = q;
            g_Q[bl*DD + t] = q;
        }
        __syncthreads();
        for (int o = t; o < 3*DD; o += 128) {
            const float* src = (o < DD) ? Qs : xr;
            const float4* w4 = (const float4*)(ipw + ((long)b1*3*DD + o) * DD);
            const float4* s4 = (const float4*)src;
            float acc = 0.f;
            #pragma unroll
            for (int kk = 0; kk < 16; kk++) {
                float4 ww = w4[kk], x = s4[kk];
                acc += ww.x*x.x + ww.y*x.y + ww.z*x.z + ww.w*x.w;
            }
            acc += ipb[b1*3*DD + o];
            if      (o < DD)   g_q[bl*DD + o      ] = acc;
            else if (o < 2*DD) g_k[bl*DD + o - 64 ] = acc;
            else               g_v[bl*DD + o - 128] = acc;
        }
        return;
    }

    if (t < DD) {
        float lf = (xr[t] - mv[0]) * mv[1] * lls[t] + llb[t];
        part[t]      = lf * E[(long)pos[bl]*DD + t];
        part[t + 64] = lf * E[(long)neg[bl]*DD + t];
    }
    __syncthreads();
    if (t < 32) {
        float s = part[t] + part[t+32];
        #pragma unroll
        for (int o = 16; o; o >>= 1) s += __shfl_xor_sync(0xffffffffu, s, o);
        if (t == 0) out[bl] = s;
    } else if (t < 64) {
        int tn = t - 32;
        float s = part[64 + tn] + part[96 + tn];
        #pragma unroll
        for (int o = 16; o; o >>= 1) s += __shfl_xor_sync(0xffffffffu, s, o);
        if (tn == 0) out[BL + bl] = s;
    }
}

// ---------------- launch ------------------------------------------------------
extern "C" void kernel_launch(void* const* d_in, const int* in_sizes, int n_in,
                              void* d_out, int out_size)
{
    const float* uemb = (const float*)d_in[0];
    const float* E    = (const float*)d_in[1];
    const float* rel  = (const float*)d_in[2];
    const float* Wt   = (const float*)d_in[3];
    const float* W1   = (const float*)d_in[4];
    const float* W2   = (const float*)d_in[5];
    const float* pemb = (const float*)d_in[6];
    const float* lnas = (const float*)d_in[7];
    const float* lnab = (const float*)d_in[8];
    const float* ipw  = (const float*)d_in[9];
    const float* ipb  = (const float*)d_in[10];
    const float* opw  = (const float*)d_in[11];
    const float* opb  = (const float*)d_in[12];
    const float* fs   = (const float*)d_in[13];
    const float* fb   = (const float*)d_in[14];
    const float* c1w  = (const float*)d_in[15];
    const float* c1b  = (const float*)d_in[16];
    const float* c2w  = (const float*)d_in[17];
    const float* c2b  = (const float*)d_in[18];
    const float* lls  = (const float*)d_in[19];
    const float* llb  = (const float*)d_in[20];
    const int*   user = (const int*)d_in[21];
    const int*   seq  = (const int*)d_in[22];
    const int*   pos  = (const int*)d_in[23];
    const int*   neg  = (const int*)d_in[24];
    const int*   mh   = (const int*)d_in[25];
    const int*   mr   = (const int*)d_in[26];
    const int*   mt   = (const int*)d_in[27];
    float* out = (float*)d_out;

    for (int hop = 0; hop < NHOP; hop++) {
        kv_rip<<<320, 256>>>(rel, E, seq, hop);
        kh_rip<<<BL, 256>>>(E, Wt, mh, mr, mt, seq, hop, hop == NHOP - 1);
    }
    ks_rip<<<BB, 128>>>(W1, W2, uemb, user, pemb, E, seq);
    kq_rip<<<BL, 128>>>(lnas, lnab, ipw, ipb, 0);
    for (int bb = 0; bb < NBLK; bb++) {
        kam_rip<<<BL, 128>>>(opw, opb, fs, fb, c1w, c1b, c2w, c2b, bb,
                             bb == NBLK - 1, E, lls, llb, pos, neg, out,
                             lnas, lnab, ipw, ipb);
    }
}